// round 2
// baseline (speedup 1.0000x reference)
#include <cuda_runtime.h>

#define Tn 128
#define Bn 8
#define En 256
#define Hn 512
#define G4 2048
#define NB2 128
#define NT2 128
#define WSTR 516   // 512 + pad(4) -> 16B aligned rows, conflict-free

// ---------------- device scratch ----------------
__device__ float g_xs[Tn * Bn * G4];   // emb@Wih_s + b_s, layout [(t*8+b)*2048 + col]
__device__ float g_xt[Tn * Bn * G4];   // emb@Wih_t + b_t
__device__ float g_h[2][Bn * Hn];      // double-buffered recurrent state
__device__ unsigned int g_leaf[8 * 64];  // 8 leaf counters, 256B apart (distinct LTS slices)

// ---------------- helpers ----------------
__device__ __forceinline__ unsigned long long fma2(unsigned long long a,
                                                   unsigned long long b,
                                                   unsigned long long c) {
    unsigned long long d;
    asm("fma.rn.f32x2 %0, %1, %2, %3;" : "=l"(d) : "l"(a), "l"(b), "l"(c));
    return d;
}
__device__ __forceinline__ float2 up2(unsigned long long a) {
    float2 f;
    asm("mov.b64 {%0, %1}, %2;" : "=f"(f.x), "=f"(f.y) : "l"(a));
    return f;
}
__device__ __forceinline__ float sigm(float x) { return 1.f / (1.f + expf(-x)); }

// ---------------- kernel 1: gathered input GEMM (emb @ Wih + bias), both matrices ----------------
// M=1024 (rows = t*8+b), N=2048, K=256. BM=BN=128, BK=16, 256 threads, 8x8/thread.
// z = 0 -> (Wih_s, b_s) -> g_xs ; z = 1 -> (Wih_t, b_t) -> g_xt
__global__ void __launch_bounds__(256) input_gemm(const int* __restrict__ tokens,
                                                  const float* __restrict__ etab,
                                                  const float* __restrict__ W0,
                                                  const float* __restrict__ bias0,
                                                  const float* __restrict__ W1,
                                                  const float* __restrict__ bias1) {
    __shared__ float As[16][128];
    __shared__ float Bs[16][128];
    const int which = blockIdx.z;
    const float* W    = which ? W1 : W0;
    const float* bias = which ? bias1 : bias0;
    float* outp = which ? g_xt : g_xs;

    // reset barrier counters for the LSTM kernel (runs strictly before it)
    if (blockIdx.x == 0 && blockIdx.y == 0 && threadIdx.x < 8)
        g_leaf[threadIdx.x * 64] = 0u;

    const int m0 = blockIdx.y * 128;
    const int n0 = blockIdx.x * 128;
    const int tid = threadIdx.x;
    const int tr = tid >> 4, tc = tid & 15;

    float acc[8][8];
#pragma unroll
    for (int i = 0; i < 8; i++)
#pragma unroll
        for (int j = 0; j < 8; j++) acc[i][j] = 0.f;

    const int mA0 = tid >> 2;
    const int mA1 = (tid + 256) >> 2;
    const int kq0 = tid & 3;
    const int gm0 = m0 + mA0, gm1 = m0 + mA1;
    const long tok0 = tokens[(gm0 & 7) * Tn + (gm0 >> 3)];
    const long tok1 = tokens[(gm1 & 7) * Tn + (gm1 >> 3)];

    const int kb = tid >> 5;
    const int nq = tid & 31;

    for (int k0 = 0; k0 < En; k0 += 16) {
        float4 a0 = *(const float4*)&etab[tok0 * En + k0 + kq0 * 4];
        float4 a1 = *(const float4*)&etab[tok1 * En + k0 + kq0 * 4];
        As[kq0 * 4 + 0][mA0] = a0.x; As[kq0 * 4 + 1][mA0] = a0.y;
        As[kq0 * 4 + 2][mA0] = a0.z; As[kq0 * 4 + 3][mA0] = a0.w;
        As[kq0 * 4 + 0][mA1] = a1.x; As[kq0 * 4 + 1][mA1] = a1.y;
        As[kq0 * 4 + 2][mA1] = a1.z; As[kq0 * 4 + 3][mA1] = a1.w;

        *(float4*)&Bs[kb][nq * 4]     = *(const float4*)&W[(k0 + kb) * G4 + n0 + nq * 4];
        *(float4*)&Bs[kb + 8][nq * 4] = *(const float4*)&W[(k0 + kb + 8) * G4 + n0 + nq * 4];
        __syncthreads();

#pragma unroll
        for (int k = 0; k < 16; k++) {
            float av[8], bv[8];
            *(float4*)&av[0] = *(const float4*)&As[k][tr * 4];
            *(float4*)&av[4] = *(const float4*)&As[k][64 + tr * 4];
            *(float4*)&bv[0] = *(const float4*)&Bs[k][tc * 4];
            *(float4*)&bv[4] = *(const float4*)&Bs[k][64 + tc * 4];
#pragma unroll
            for (int i = 0; i < 8; i++)
#pragma unroll
                for (int j = 0; j < 8; j++) acc[i][j] += av[i] * bv[j];
        }
        __syncthreads();
    }

#pragma unroll
    for (int i = 0; i < 8; i++) {
        int m = m0 + ((i < 4) ? (tr * 4 + i) : (64 + tr * 4 + i - 4));
#pragma unroll
        for (int jh = 0; jh < 2; jh++) {
            int n = n0 + tc * 4 + jh * 64;
            float4 v;
            v.x = acc[i][jh * 4 + 0] + __ldg(&bias[n + 0]);
            v.y = acc[i][jh * 4 + 1] + __ldg(&bias[n + 1]);
            v.z = acc[i][jh * 4 + 2] + __ldg(&bias[n + 2]);
            v.w = acc[i][jh * 4 + 3] + __ldg(&bias[n + 3]);
            *(float4*)&outp[(long)m * G4 + n] = v;
        }
    }
}

// ---------------- kernel 2: persistent dual-LSTM ----------------
// 128 blocks x 128 threads. Block bl owns h-units [bl*4, bl*4+4) => 16 gate cols.
// thread: c = tid>>3 (gate-col within block), b = tid&7 (batch).
// Warp = 4 cols x 8 batches: weight LDS broadcasts 8-way, h LDS covers 32 banks.
__global__ void __launch_bounds__(NT2) lstm_kernel(const float* __restrict__ Whh_s,
                                                   const float* __restrict__ Whh_t,
                                                   const float* __restrict__ Wmh_t,
                                                   float* __restrict__ out) {
    extern __shared__ float sm[];
    float* ws  = sm;                 // [16][WSTR] Whh_s slice (later reused for Wmh_t)
    float* wt  = ws + 16 * WSTR;     // [16][WSTR] Whh_t slice
    float* hs  = wt + 16 * WSTR;     // [8][WSTR]  current h
    float* pre = hs + 8 * WSTR;      // [16][8]    pre-activations, pre[c*8+b]
    float* cst = pre + 128;          // [32]       c-state (b*4 + j)
    float* rcs = cst + 32;           // [16][8]    h_last @ Wmh_t slice

    const int tid = threadIdx.x;
    const int bl  = blockIdx.x;
    const int c   = tid >> 3;
    const int b   = tid & 7;
    const int col = (c >> 2) * Hn + bl * 4 + (c & 3);

    // load recurrent weight slices (one-time)
    for (int i = tid; i < 16 * Hn; i += NT2) {
        int cc = i & 15, k = i >> 4;
        int cl = (cc >> 2) * Hn + bl * 4 + (cc & 3);
        ws[cc * WSTR + k] = Whh_s[(long)k * G4 + cl];
        wt[cc * WSTR + k] = Whh_t[(long)k * G4 + cl];
    }
    if (tid < 32) {
        int bb = tid >> 2, j = tid & 3;
        __stcg(&g_h[0][bb * Hn + bl * 4 + j], 0.f);
        cst[tid] = 0.f;
    }

    int nbar = 0;
    auto gbar = [&]() {
        __syncthreads();
        if (tid == 0) {
            nbar++;
            asm volatile("red.release.gpu.global.add.u32 [%0], 1;"
                         :: "l"(&g_leaf[(bl & 7) * 64]) : "memory");
            const unsigned target = (unsigned)(NB2 * nbar);
            unsigned s;
            do {
                s = 0;
#pragma unroll
                for (int i = 0; i < 8; i++) {
                    unsigned v;
                    asm volatile("ld.acquire.gpu.global.u32 %0, [%1];"
                                 : "=r"(v) : "l"(&g_leaf[i * 64]) : "memory");
                    s += v;
                }
            } while (s < target);
        }
        __syncthreads();
    };

    auto load_h = [&](int rp) {
#pragma unroll
        for (int i = 0; i < 8; i++) {
            int idx = tid + i * NT2;          // 0..1023
            int bb = idx >> 7, k4 = idx & 127;
            float4 v = __ldcg((const float4*)&g_h[rp][bb * Hn + k4 * 4]);
            *(float4*)&hs[bb * WSTR + k4 * 4] = v;
        }
    };

    auto do_step = [&](const float* wsel, const float* xbase, const float* rcp,
                       int t, int rp, int wp, float* outp, bool dobar) {
        float xval = __ldg(&xbase[(long)(t * Bn + b) * G4 + col]);
        if (rcp) xval += rcp[c * 8 + b];
        load_h(rp);
        __syncthreads();

        const float* hrow = hs + b * WSTR;
        const float* wrow = wsel + c * WSTR;
        unsigned long long acc0 = 0ull, acc1 = 0ull;
#pragma unroll 8
        for (int kq = 0; kq < Hn / 4; kq++) {
            ulonglong2 hv = *(const ulonglong2*)(hrow + kq * 4);
            ulonglong2 wv = *(const ulonglong2*)(wrow + kq * 4);
            acc0 = fma2(hv.x, wv.x, acc0);
            acc1 = fma2(hv.y, wv.y, acc1);
        }
        float2 f0 = up2(acc0), f1 = up2(acc1);
        pre[c * 8 + b] = xval + (f0.x + f1.x) + (f0.y + f1.y);
        __syncthreads();

        if (tid < 32) {
            int bb = tid >> 2, j = tid & 3;
            float iv = pre[(0  + j) * 8 + bb];
            float fv = pre[(4  + j) * 8 + bb];
            float gv = pre[(8  + j) * 8 + bb];
            float ov = pre[(12 + j) * 8 + bb];
            float cn = sigm(fv) * cst[tid] + sigm(iv) * tanhf(gv);
            float hn = sigm(ov) * tanhf(cn);
            cst[tid] = cn;
            __stcg(&g_h[wp][bb * Hn + bl * 4 + j], hn);
            if (outp) outp[(long)(bb * Tn + t) * Hn + bl * 4 + j] = hn;
        }
        if (dobar) gbar();
    };

    gbar();  // h=0 visible everywhere

    // ---- shared LSTM (attention is identity: softmax sums to 1 over the
    //      broadcast axis of h_shared, so Rt == h_last, constant) ----
    for (int t = 0; t < Tn; t++)
        do_step(ws, g_xs, nullptr, t, t & 1, (t & 1) ^ 1, nullptr, true);

    // snapshot h_last (in g_h[0]) into smem
    load_h(0);
    __syncthreads();
    gbar();  // all blocks hold h_last locally -> safe to overwrite g_h[0]

    if (tid < 32) {
        int bb = tid >> 2, j = tid & 3;
        __stcg(&g_h[0][bb * Hn + bl * 4 + j], 0.f);
        cst[tid] = 0.f;
    }
    // rc = h_last @ Wmh_t (constant across task steps): stage W slice via smem (ws is dead)
    for (int i = tid; i < 16 * Hn; i += NT2) {
        int cc = i & 15, k = i >> 4;
        int cl = (cc >> 2) * Hn + bl * 4 + (cc & 3);
        ws[cc * WSTR + k] = Wmh_t[(long)k * G4 + cl];
    }
    __syncthreads();
    {
        const float* hrow = hs + b * WSTR;
        const float* wrow = ws + c * WSTR;
        unsigned long long acc0 = 0ull, acc1 = 0ull;
#pragma unroll 8
        for (int kq = 0; kq < Hn / 4; kq++) {
            ulonglong2 hv = *(const ulonglong2*)(hrow + kq * 4);
            ulonglong2 wv = *(const ulonglong2*)(wrow + kq * 4);
            acc0 = fma2(hv.x, wv.x, acc0);
            acc1 = fma2(hv.y, wv.y, acc1);
        }
        float2 f0 = up2(acc0), f1 = up2(acc1);
        rcs[c * 8 + b] = (f0.x + f1.x) + (f0.y + f1.y);
    }
    gbar();  // zeros published (rcs is block-local)

    // ---- task LSTM, writing output (skip barrier on final step) ----
    for (int t = 0; t < Tn; t++)
        do_step(wt, g_xt, rcs, t, t & 1, (t & 1) ^ 1, out, t != Tn - 1);
}

// ---------------- launch ----------------
extern "C" void kernel_launch(void* const* d_in, const int* in_sizes, int n_in,
                              void* d_out, int out_size) {
    const int sh = (n_in == 14) ? 0 : 1;  // shift if TASK scalar was dropped
    const int*   tokens = (const int*)d_in[0];
    const float* etab   = (const float*)d_in[2 - sh];
    const float* Wih_s  = (const float*)d_in[3 - sh];
    const float* Whh_s  = (const float*)d_in[4 - sh];
    const float* b_s    = (const float*)d_in[5 - sh];
    const float* Wih_t  = (const float*)d_in[10 - sh];
    const float* Whh_t  = (const float*)d_in[11 - sh];
    const float* Wmh_t  = (const float*)d_in[12 - sh];
    const float* b_t    = (const float*)d_in[13 - sh];
    float* out = (float*)d_out;

    const int smem2 = (16 * WSTR * 2 + 8 * WSTR + 128 + 32 + 128) * (int)sizeof(float);
    cudaFuncSetAttribute(lstm_kernel, cudaFuncAttributeMaxDynamicSharedMemorySize, smem2);

    dim3 gg(G4 / 128, (Tn * Bn) / 128, 2);  // (16, 8, 2)
    input_gemm<<<gg, 256>>>(tokens, etab, Wih_s, b_s, Wih_t, b_t);
    lstm_kernel<<<NB2, NT2, smem2>>>(Whh_s, Whh_t, Wmh_t, out);
}

// round 3
// speedup vs baseline: 1.1438x; 1.1438x over previous
#include <cuda_runtime.h>

#define Tn 128
#define Bn 8
#define En 256
#define Hn 512
#define G4 2048
#define NB2 128
#define NT2 128
#define WSTR 516   // 512 + pad(4) -> 16B aligned rows, conflict-free
#define NLEAF 16
#define ARR_PER_BAR (NB2 * 32)   // 32 release-arrivals per block per barrier

// ---------------- device scratch ----------------
__device__ float g_xs[Tn * Bn * G4];   // emb@Wih_s + b_s, layout [(t*8+b)*2048 + col]
__device__ float g_xt[Tn * Bn * G4];   // emb@Wih_t + b_t
__device__ float g_h[2][Bn * Hn];      // double-buffered recurrent state
__device__ unsigned int g_leaf[NLEAF * 64];  // leaf counters, 256B apart

// ---------------- helpers ----------------
__device__ __forceinline__ unsigned long long fma2(unsigned long long a,
                                                   unsigned long long b,
                                                   unsigned long long c) {
    unsigned long long d;
    asm("fma.rn.f32x2 %0, %1, %2, %3;" : "=l"(d) : "l"(a), "l"(b), "l"(c));
    return d;
}
__device__ __forceinline__ float2 up2(unsigned long long a) {
    float2 f;
    asm("mov.b64 {%0, %1}, %2;" : "=f"(f.x), "=f"(f.y) : "l"(a));
    return f;
}
// fast, accurate-enough activations (MUFU.EX2 based, rel err ~1e-6)
__device__ __forceinline__ float sigm(float x) {
    float e = __expf(-x);
    return __frcp_rn(1.f + e);
}
__device__ __forceinline__ float tanh_f(float x) {
    float e = __expf(2.f * x);
    return 1.f - 2.f * __frcp_rn(e + 1.f);
}

// ---------------- kernel 1: gathered input GEMM (emb @ Wih + bias), both matrices ----------------
__global__ void __launch_bounds__(256) input_gemm(const int* __restrict__ tokens,
                                                  const float* __restrict__ etab,
                                                  const float* __restrict__ W0,
                                                  const float* __restrict__ bias0,
                                                  const float* __restrict__ W1,
                                                  const float* __restrict__ bias1) {
    __shared__ float As[16][128];
    __shared__ float Bs[16][128];
    const int which = blockIdx.z;
    const float* W    = which ? W1 : W0;
    const float* bias = which ? bias1 : bias0;
    float* outp = which ? g_xt : g_xs;

    // reset barrier counters for the LSTM kernel (runs strictly before it)
    if (blockIdx.x == 0 && blockIdx.y == 0 && threadIdx.x < NLEAF)
        g_leaf[threadIdx.x * 64] = 0u;

    const int m0 = blockIdx.y * 128;
    const int n0 = blockIdx.x * 128;
    const int tid = threadIdx.x;
    const int tr = tid >> 4, tc = tid & 15;

    float acc[8][8];
#pragma unroll
    for (int i = 0; i < 8; i++)
#pragma unroll
        for (int j = 0; j < 8; j++) acc[i][j] = 0.f;

    const int mA0 = tid >> 2;
    const int mA1 = (tid + 256) >> 2;
    const int kq0 = tid & 3;
    const int gm0 = m0 + mA0, gm1 = m0 + mA1;
    const long tok0 = tokens[(gm0 & 7) * Tn + (gm0 >> 3)];
    const long tok1 = tokens[(gm1 & 7) * Tn + (gm1 >> 3)];

    const int kb = tid >> 5;
    const int nq = tid & 31;

    for (int k0 = 0; k0 < En; k0 += 16) {
        float4 a0 = *(const float4*)&etab[tok0 * En + k0 + kq0 * 4];
        float4 a1 = *(const float4*)&etab[tok1 * En + k0 + kq0 * 4];
        As[kq0 * 4 + 0][mA0] = a0.x; As[kq0 * 4 + 1][mA0] = a0.y;
        As[kq0 * 4 + 2][mA0] = a0.z; As[kq0 * 4 + 3][mA0] = a0.w;
        As[kq0 * 4 + 0][mA1] = a1.x; As[kq0 * 4 + 1][mA1] = a1.y;
        As[kq0 * 4 + 2][mA1] = a1.z; As[kq0 * 4 + 3][mA1] = a1.w;

        *(float4*)&Bs[kb][nq * 4]     = *(const float4*)&W[(k0 + kb) * G4 + n0 + nq * 4];
        *(float4*)&Bs[kb + 8][nq * 4] = *(const float4*)&W[(k0 + kb + 8) * G4 + n0 + nq * 4];
        __syncthreads();

#pragma unroll
        for (int k = 0; k < 16; k++) {
            float av[8], bv[8];
            *(float4*)&av[0] = *(const float4*)&As[k][tr * 4];
            *(float4*)&av[4] = *(const float4*)&As[k][64 + tr * 4];
            *(float4*)&bv[0] = *(const float4*)&Bs[k][tc * 4];
            *(float4*)&bv[4] = *(const float4*)&Bs[k][64 + tc * 4];
#pragma unroll
            for (int i = 0; i < 8; i++)
#pragma unroll
                for (int j = 0; j < 8; j++) acc[i][j] += av[i] * bv[j];
        }
        __syncthreads();
    }

#pragma unroll
    for (int i = 0; i < 8; i++) {
        int m = m0 + ((i < 4) ? (tr * 4 + i) : (64 + tr * 4 + i - 4));
#pragma unroll
        for (int jh = 0; jh < 2; jh++) {
            int n = n0 + tc * 4 + jh * 64;
            float4 v;
            v.x = acc[i][jh * 4 + 0] + __ldg(&bias[n + 0]);
            v.y = acc[i][jh * 4 + 1] + __ldg(&bias[n + 1]);
            v.z = acc[i][jh * 4 + 2] + __ldg(&bias[n + 2]);
            v.w = acc[i][jh * 4 + 3] + __ldg(&bias[n + 3]);
            *(float4*)&outp[(long)m * G4 + n] = v;
        }
    }
}

// ---------------- barrier primitives ----------------
__device__ __forceinline__ void bar_arrive_lane(int lane) {
    // fire-and-forget release-reduction: orders THIS lane's prior stores
    asm volatile("red.release.gpu.global.add.u32 [%0], 1;"
                 :: "l"(&g_leaf[(lane & (NLEAF - 1)) * 64]) : "memory");
}
__device__ __forceinline__ void bar_poll(unsigned target) {
    // lane0-of-warp only; relaxed loads (fully overlapped), one acquire fence on exit
    unsigned s;
    do {
        s = 0;
#pragma unroll
        for (int i = 0; i < NLEAF; i++) {
            unsigned v;
            asm volatile("ld.relaxed.gpu.global.u32 %0, [%1];"
                         : "=r"(v) : "l"(&g_leaf[i * 64]) : "memory");
            s += v;
        }
    } while (s < target);
    asm volatile("fence.acq_rel.gpu;" ::: "memory");
}

// ---------------- kernel 2: persistent dual-LSTM ----------------
// 128 blocks x 128 threads. Block bl owns h-units [bl*4, bl*4+4) => 16 gate cols.
// thread: c = tid>>3 (gate-col within block), b = tid&7 (batch).
__global__ void __launch_bounds__(NT2) lstm_kernel(const float* __restrict__ Whh_s,
                                                   const float* __restrict__ Whh_t,
                                                   const float* __restrict__ Wmh_t,
                                                   float* __restrict__ out) {
    extern __shared__ float sm[];
    float* ws  = sm;                 // [16][WSTR] Whh_s slice (later reused for Wmh_t)
    float* wt  = ws + 16 * WSTR;     // [16][WSTR] Whh_t slice
    float* hs  = wt + 16 * WSTR;     // [8][WSTR]  current h
    float* pre = hs + 8 * WSTR;      // [16][8]    pre-activations
    float* cst = pre + 128;          // [32]       c-state
    float* rcs = cst + 32;           // [16][8]    h_last @ Wmh_t slice

    const int tid  = threadIdx.x;
    const int bl   = blockIdx.x;
    const int lane = tid & 31;
    const int c    = tid >> 3;
    const int b    = tid & 7;
    const int col  = (c >> 2) * Hn + bl * 4 + (c & 3);

    // load recurrent weight slices (one-time)
    for (int i = tid; i < 16 * Hn; i += NT2) {
        int cc = i & 15, k = i >> 4;
        int cl = (cc >> 2) * Hn + bl * 4 + (cc & 3);
        ws[cc * WSTR + k] = Whh_s[(long)k * G4 + cl];
        wt[cc * WSTR + k] = Whh_t[(long)k * G4 + cl];
    }
    if (tid < 32) {
        int bb = tid >> 2, j = tid & 3;
        __stcg(&g_h[0][bb * Hn + bl * 4 + j], 0.f);
        cst[tid] = 0.f;
    }

    unsigned nbar = 0;

    // full barrier used outside the hot loop
    auto gbar = [&]() {
        __syncthreads();
        nbar++;
        if (tid < 32) bar_arrive_lane(tid);
        if (lane == 0) bar_poll(ARR_PER_BAR * nbar);
        __syncwarp();
    };

    auto load_h = [&](int rp) {
#pragma unroll
        for (int i = 0; i < 8; i++) {
            int idx = tid + i * NT2;          // 0..1023
            int bb = idx >> 7, k4 = idx & 127;
            float4 v = __ldcg((const float4*)&g_h[rp][bb * Hn + k4 * 4]);
            *(float4*)&hs[bb * WSTR + k4 * 4] = v;
        }
    };

    auto do_step = [&](const float* wsel, const float* xbase, const float* rcp,
                       int t, int rp, int wp, float* outp) {
        float xval = __ldg(&xbase[(long)(t * Bn + b) * G4 + col]);
        if (rcp) xval += rcp[c * 8 + b];
        load_h(rp);
        __syncthreads();

        const float* hrow = hs + b * WSTR;
        const float* wrow = wsel + c * WSTR;
        unsigned long long acc0 = 0ull, acc1 = 0ull;
#pragma unroll 16
        for (int kq = 0; kq < Hn / 4; kq++) {
            ulonglong2 hv = *(const ulonglong2*)(hrow + kq * 4);
            ulonglong2 wv = *(const ulonglong2*)(wrow + kq * 4);
            acc0 = fma2(hv.x, wv.x, acc0);
            acc1 = fma2(hv.y, wv.y, acc1);
        }
        float2 f0 = up2(acc0), f1 = up2(acc1);
        pre[c * 8 + b] = xval + (f0.x + f1.x) + (f0.y + f1.y);
        __syncthreads();

        nbar++;
        if (tid < 32) {
            int bb = tid >> 2, j = tid & 3;
            float iv = pre[(0  + j) * 8 + bb];
            float fv = pre[(4  + j) * 8 + bb];
            float gv = pre[(8  + j) * 8 + bb];
            float ov = pre[(12 + j) * 8 + bb];
            float cn = sigm(fv) * cst[tid] + sigm(iv) * tanh_f(gv);
            float hn = sigm(ov) * tanh_f(cn);
            cst[tid] = cn;
            __stcg(&g_h[wp][bb * Hn + bl * 4 + j], hn);
            bar_arrive_lane(tid);   // release orders this lane's h-store
            if (outp) outp[(long)(bb * Tn + t) * Hn + bl * 4 + j] = hn;
        }
        if (lane == 0) bar_poll(ARR_PER_BAR * nbar);
        __syncwarp();
    };

    gbar();  // h=0 visible everywhere

    // ---- shared LSTM (attention is identity: softmax over the broadcast axis
    //      of h_shared sums to 1, so Rt == h_last, constant) ----
    for (int t = 0; t < Tn; t++)
        do_step(ws, g_xs, nullptr, t, t & 1, (t & 1) ^ 1, nullptr);

    // snapshot h_last (in g_h[0]) into smem
    load_h(0);
    __syncthreads();
    gbar();  // all blocks hold h_last locally -> safe to overwrite g_h[0]

    if (tid < 32) {
        int bb = tid >> 2, j = tid & 3;
        __stcg(&g_h[0][bb * Hn + bl * 4 + j], 0.f);
        cst[tid] = 0.f;
    }
    // rc = h_last @ Wmh_t (constant across task steps): stage W slice via smem
    for (int i = tid; i < 16 * Hn; i += NT2) {
        int cc = i & 15, k = i >> 4;
        int cl = (cc >> 2) * Hn + bl * 4 + (cc & 3);
        ws[cc * WSTR + k] = Wmh_t[(long)k * G4 + cl];
    }
    __syncthreads();
    {
        const float* hrow = hs + b * WSTR;
        const float* wrow = ws + c * WSTR;
        unsigned long long acc0 = 0ull, acc1 = 0ull;
#pragma unroll 16
        for (int kq = 0; kq < Hn / 4; kq++) {
            ulonglong2 hv = *(const ulonglong2*)(hrow + kq * 4);
            ulonglong2 wv = *(const ulonglong2*)(wrow + kq * 4);
            acc0 = fma2(hv.x, wv.x, acc0);
            acc1 = fma2(hv.y, wv.y, acc1);
        }
        float2 f0 = up2(acc0), f1 = up2(acc1);
        rcs[c * 8 + b] = (f0.x + f1.x) + (f0.y + f1.y);
    }
    gbar();  // zeros published (rcs is block-local)

    // ---- task LSTM, writing output ----
    for (int t = 0; t < Tn; t++)
        do_step(wt, g_xt, rcs, t, t & 1, (t & 1) ^ 1, out);
}

// ---------------- launch ----------------
extern "C" void kernel_launch(void* const* d_in, const int* in_sizes, int n_in,
                              void* d_out, int out_size) {
    const int sh = (n_in == 14) ? 0 : 1;  // shift if TASK scalar was dropped
    const int*   tokens = (const int*)d_in[0];
    const float* etab   = (const float*)d_in[2 - sh];
    const float* Wih_s  = (const float*)d_in[3 - sh];
    const float* Whh_s  = (const float*)d_in[4 - sh];
    const float* b_s    = (const float*)d_in[5 - sh];
    const float* Wih_t  = (const float*)d_in[10 - sh];
    const float* Whh_t  = (const float*)d_in[11 - sh];
    const float* Wmh_t  = (const float*)d_in[12 - sh];
    const float* b_t    = (const float*)d_in[13 - sh];
    float* out = (float*)d_out;

    const int smem2 = (16 * WSTR * 2 + 8 * WSTR + 128 + 32 + 128) * (int)sizeof(float);
    cudaFuncSetAttribute(lstm_kernel, cudaFuncAttributeMaxDynamicSharedMemorySize, smem2);

    dim3 gg(G4 / 128, (Tn * Bn) / 128, 2);  // (16, 8, 2)
    input_gemm<<<gg, 256>>>(tokens, etab, Wih_s, b_s, Wih_t, b_t);
    lstm_kernel<<<NB2, NT2, smem2>>>(Whh_s, Whh_t, Wmh_t, out);
}

// round 4
// speedup vs baseline: 1.9642x; 1.7173x over previous
#include <cuda_runtime.h>

#define Tn 128
#define Bn 8
#define En 256
#define Hn 512
#define G4 2048
#define NB2 128
#define NT2 128
#define WSTR 516   // 512 + pad -> 16B-aligned rows
#define NLEAF 8
#define ARRB 8     // release-arrivals per block per barrier
typedef unsigned long long ull;

// ---------------- device scratch ----------------
__device__ float g_xs[Tn * Bn * G4];   // emb@Wih_s + b_s, [(t*8+b)*2048 + col]
__device__ float g_xt[Tn * Bn * G4];   // emb@Wih_t + b_t
__device__ float g_h[2][Bn * Hn];      // double-buffered recurrent state
__device__ unsigned int g_leaf[NLEAF * 64];  // leaf counters, 256B apart

// ---------------- helpers ----------------
__device__ __forceinline__ ull fma2(ull a, ull b, ull c) {
    ull d;
    asm("fma.rn.f32x2 %0, %1, %2, %3;" : "=l"(d) : "l"(a), "l"(b), "l"(c));
    return d;
}
__device__ __forceinline__ float2 up2(ull a) {
    float2 f;
    asm("mov.b64 {%0, %1}, %2;" : "=f"(f.x), "=f"(f.y) : "l"(a));
    return f;
}
__device__ __forceinline__ float sigm(float x) {
    return __frcp_rn(1.f + __expf(-x));
}
__device__ __forceinline__ float tanh_f(float x) {
    return 1.f - 2.f * __frcp_rn(__expf(2.f * x) + 1.f);
}

__device__ __forceinline__ void bar_arrive(int lane) {
    asm volatile("red.release.gpu.global.add.u32 [%0], 1;"
                 :: "l"(&g_leaf[lane * 64]) : "memory");
}
__device__ __forceinline__ void bar_poll(unsigned target) {
    unsigned s;
    do {
        s = 0;
#pragma unroll
        for (int i = 0; i < NLEAF; i++) {
            unsigned v;
            asm volatile("ld.relaxed.gpu.global.u32 %0, [%1];"
                         : "=r"(v) : "l"(&g_leaf[i * 64]) : "memory");
            s += v;
        }
    } while (s < target);
    asm volatile("fence.acq_rel.gpu;" ::: "memory");
}

// stage-1 dot: thread (kg,c) -> 8 partial sums over its 64-k slice, weights in regs
__device__ __forceinline__ void stage1_dot(const ull* wreg, const float* hs,
                                           float* red, int kg, int c) {
    float part[8];
#pragma unroll
    for (int b = 0; b < 8; b++) {
        const float* hb = hs + b * WSTR + kg * 64;
        ull a0 = 0ull, a1 = 0ull;
#pragma unroll
        for (int kq = 0; kq < 16; kq++) {
            ulonglong2 hv = *(const ulonglong2*)(hb + kq * 4);
            a0 = fma2(hv.x, wreg[2 * kq], a0);
            a1 = fma2(hv.y, wreg[2 * kq + 1], a1);
        }
        float2 f0 = up2(a0), f1 = up2(a1);
        part[b] = (f0.x + f1.x) + (f0.y + f1.y);
    }
    *(float4*)&red[kg * 128 + c * 8]     = make_float4(part[0], part[1], part[2], part[3]);
    *(float4*)&red[kg * 128 + c * 8 + 4] = make_float4(part[4], part[5], part[6], part[7]);
}
__device__ __forceinline__ float stage2_sum(const float* red, int tid, float xv) {
    float p = xv;
#pragma unroll
    for (int g = 0; g < 8; g++) p += red[g * 128 + tid];  // tid == c2*8+b2
    return p;
}

// ---------------- kernel 1: gathered input GEMM (both matrices via z) ----------------
__global__ void __launch_bounds__(256) input_gemm(const int* __restrict__ tokens,
                                                  const float* __restrict__ etab,
                                                  const float* __restrict__ W0,
                                                  const float* __restrict__ bias0,
                                                  const float* __restrict__ W1,
                                                  const float* __restrict__ bias1) {
    __shared__ float As[16][128];
    __shared__ float Bs[16][128];
    const int which = blockIdx.z;
    const float* W    = which ? W1 : W0;
    const float* bias = which ? bias1 : bias0;
    float* outp = which ? g_xt : g_xs;

    if (blockIdx.x == 0 && blockIdx.y == 0 && threadIdx.x < NLEAF)
        g_leaf[threadIdx.x * 64] = 0u;

    const int m0 = blockIdx.y * 128;
    const int n0 = blockIdx.x * 128;
    const int tid = threadIdx.x;
    const int tr = tid >> 4, tc = tid & 15;

    float acc[8][8];
#pragma unroll
    for (int i = 0; i < 8; i++)
#pragma unroll
        for (int j = 0; j < 8; j++) acc[i][j] = 0.f;

    const int mA0 = tid >> 2;
    const int mA1 = (tid + 256) >> 2;
    const int kq0 = tid & 3;
    const int gm0 = m0 + mA0, gm1 = m0 + mA1;
    const long tok0 = tokens[(gm0 & 7) * Tn + (gm0 >> 3)];
    const long tok1 = tokens[(gm1 & 7) * Tn + (gm1 >> 3)];

    const int kb = tid >> 5;
    const int nq = tid & 31;

    for (int k0 = 0; k0 < En; k0 += 16) {
        float4 a0 = *(const float4*)&etab[tok0 * En + k0 + kq0 * 4];
        float4 a1 = *(const float4*)&etab[tok1 * En + k0 + kq0 * 4];
        As[kq0 * 4 + 0][mA0] = a0.x; As[kq0 * 4 + 1][mA0] = a0.y;
        As[kq0 * 4 + 2][mA0] = a0.z; As[kq0 * 4 + 3][mA0] = a0.w;
        As[kq0 * 4 + 0][mA1] = a1.x; As[kq0 * 4 + 1][mA1] = a1.y;
        As[kq0 * 4 + 2][mA1] = a1.z; As[kq0 * 4 + 3][mA1] = a1.w;

        *(float4*)&Bs[kb][nq * 4]     = *(const float4*)&W[(k0 + kb) * G4 + n0 + nq * 4];
        *(float4*)&Bs[kb + 8][nq * 4] = *(const float4*)&W[(k0 + kb + 8) * G4 + n0 + nq * 4];
        __syncthreads();

#pragma unroll
        for (int k = 0; k < 16; k++) {
            float av[8], bv[8];
            *(float4*)&av[0] = *(const float4*)&As[k][tr * 4];
            *(float4*)&av[4] = *(const float4*)&As[k][64 + tr * 4];
            *(float4*)&bv[0] = *(const float4*)&Bs[k][tc * 4];
            *(float4*)&bv[4] = *(const float4*)&Bs[k][64 + tc * 4];
#pragma unroll
            for (int i = 0; i < 8; i++)
#pragma unroll
                for (int j = 0; j < 8; j++) acc[i][j] += av[i] * bv[j];
        }
        __syncthreads();
    }

#pragma unroll
    for (int i = 0; i < 8; i++) {
        int m = m0 + ((i < 4) ? (tr * 4 + i) : (64 + tr * 4 + i - 4));
#pragma unroll
        for (int jh = 0; jh < 2; jh++) {
            int n = n0 + tc * 4 + jh * 64;
            float4 v;
            v.x = acc[i][jh * 4 + 0] + __ldg(&bias[n + 0]);
            v.y = acc[i][jh * 4 + 1] + __ldg(&bias[n + 1]);
            v.z = acc[i][jh * 4 + 2] + __ldg(&bias[n + 2]);
            v.w = acc[i][jh * 4 + 3] + __ldg(&bias[n + 3]);
            *(float4*)&outp[(long)m * G4 + n] = v;
        }
    }
}

// ---------------- kernel 2: persistent dual-LSTM, weights in registers ----------------
__global__ void __launch_bounds__(NT2) lstm_kernel(const float* __restrict__ Whh_s,
                                                   const float* __restrict__ Whh_t,
                                                   const float* __restrict__ Wmh_t,
                                                   float* __restrict__ out) {
    extern __shared__ float sm[];
    float* wstage = sm;                  // [16][WSTR] weight staging (transient)
    float* hs     = wstage + 16 * WSTR;  // [8][WSTR]  current h
    float* red    = hs + 8 * WSTR;       // [8][128]   k-group partials
    float* prebuf = red + 1024;          // [128]      pre-activations (c*8+b)
    float* cst    = prebuf + 128;        // [32]       c-state
    float* hsnew  = cst + 32;            // [32]       new h staging

    const int tid = threadIdx.x;
    const int bl  = blockIdx.x;
    const int kg  = tid >> 4, c  = tid & 15;   // stage-1 identity
    const int c2  = tid >> 3, b2 = tid & 7;    // stage-2 identity
    const int col2 = (c2 >> 2) * Hn + bl * 4 + (c2 & 3);

    ull wreg[32];

    auto stageW = [&](const float* W) {
        __syncthreads();
        for (int i = tid; i < 16 * Hn; i += NT2) {
            int cc = i & 15, k = i >> 4;
            int cl = (cc >> 2) * Hn + bl * 4 + (cc & 3);
            wstage[cc * WSTR + k] = W[(long)k * G4 + cl];
        }
        __syncthreads();
#pragma unroll
        for (int i = 0; i < 32; i++)
            wreg[i] = *(const ull*)(wstage + c * WSTR + kg * 64 + 2 * i);
    };

    unsigned nbar = 0;
    auto gbar = [&]() {
        __syncthreads();
        if (tid < ARRB) bar_arrive(tid);
        nbar++;
        if (tid == 0) bar_poll((unsigned)(ARRB * NB2) * nbar);
        __syncthreads();
    };

    auto load_h = [&](int rp) {
#pragma unroll
        for (int i = 0; i < 8; i++) {
            int idx = tid + i * NT2;
            int bb = idx >> 7, k4 = idx & 127;
            float4 v = __ldcg((const float4*)&g_h[rp][bb * Hn + k4 * 4]);
            *(float4*)&hs[bb * WSTR + k4 * 4] = v;
        }
    };

    auto do_step = [&](const float* xbase, float rcv, int t, int rp, int wp,
                       float* outp, bool dobar) {
        float xval = __ldg(&xbase[(long)(t * Bn + b2) * G4 + col2]) + rcv;
        load_h(rp);
        __syncthreads();
        stage1_dot(wreg, hs, red, kg, c);
        __syncthreads();
        prebuf[tid] = stage2_sum(red, tid, xval);
        __syncthreads();
        if (tid < 32) {
            int bb = tid >> 2, j = tid & 3;
            float iv = prebuf[(0  + j) * 8 + bb];
            float fv = prebuf[(4  + j) * 8 + bb];
            float gv = prebuf[(8  + j) * 8 + bb];
            float ov = prebuf[(12 + j) * 8 + bb];
            float cn = sigm(fv) * cst[tid] + sigm(iv) * tanh_f(gv);
            float hn = sigm(ov) * tanh_f(cn);
            cst[tid] = cn;
            hsnew[bb * 4 + j] = hn;
            __syncwarp();
            if (tid < 8) {
                float4 v = *(const float4*)&hsnew[tid * 4];
                __stcg((float4*)&g_h[wp][tid * Hn + bl * 4], v);
                if (outp) __stcg((float4*)&outp[(long)(tid * Tn + t) * Hn + bl * 4], v);
                bar_arrive(tid);   // release orders this lane's g_h store
            }
        }
        if (dobar) {
            nbar++;
            if (tid == 0) bar_poll((unsigned)(ARRB * NB2) * nbar);
            __syncthreads();
        }
    };

    // ---- init: weights for shared phase, h=0, c=0 ----
    stageW(Whh_s);
    if (tid < 8)
        __stcg((float4*)&g_h[0][tid * Hn + bl * 4], make_float4(0.f, 0.f, 0.f, 0.f));
    if (tid < 32) cst[tid] = 0.f;
    gbar();

    // ---- shared LSTM (attention is identity: softmax over the broadcast axis
    //      of h_shared sums to 1, so Rt == h_last, constant) ----
    for (int t = 0; t < Tn; t++)
        do_step(g_xs, 0.f, t, t & 1, (t & 1) ^ 1, nullptr, true);

    // snapshot h_last (in g_h[0]) into smem
    load_h(0);
    __syncthreads();
    gbar();  // everyone holds h_last -> safe to overwrite g_h[0]

    if (tid < 8)
        __stcg((float4*)&g_h[0][tid * Hn + bl * 4], make_float4(0.f, 0.f, 0.f, 0.f));
    if (tid < 32) cst[tid] = 0.f;

    // rc = h_last @ Wmh_t (constant across task steps), per stage-2 identity
    stageW(Wmh_t);
    stage1_dot(wreg, hs, red, kg, c);
    __syncthreads();
    float rcv = stage2_sum(red, tid, 0.f);
    stageW(Whh_t);   // leading syncthreads protects red reads above
    gbar();          // zeros published

    // ---- task LSTM, writing output ----
    for (int t = 0; t < Tn; t++)
        do_step(g_xt, rcv, t, t & 1, (t & 1) ^ 1, out, t != Tn - 1);
}

// ---------------- launch ----------------
extern "C" void kernel_launch(void* const* d_in, const int* in_sizes, int n_in,
                              void* d_out, int out_size) {
    const int sh = (n_in == 14) ? 0 : 1;
    const int*   tokens = (const int*)d_in[0];
    const float* etab   = (const float*)d_in[2 - sh];
    const float* Wih_s  = (const float*)d_in[3 - sh];
    const float* Whh_s  = (const float*)d_in[4 - sh];
    const float* b_s    = (const float*)d_in[5 - sh];
    const float* Wih_t  = (const float*)d_in[10 - sh];
    const float* Whh_t  = (const float*)d_in[11 - sh];
    const float* Wmh_t  = (const float*)d_in[12 - sh];
    const float* b_t    = (const float*)d_in[13 - sh];
    float* out = (float*)d_out;

    const int smem2 = (16 * WSTR + 8 * WSTR + 1024 + 128 + 32 + 32) * (int)sizeof(float);
    cudaFuncSetAttribute(lstm_kernel, cudaFuncAttributeMaxDynamicSharedMemorySize, smem2);

    dim3 gg(G4 / 128, (Tn * Bn) / 128, 2);  // (16, 8, 2)
    input_gemm<<<gg, 256>>>(tokens, etab, Wih_s, b_s, Wih_t, b_t);
    lstm_kernel<<<NB2, NT2, smem2>>>(Whh_s, Whh_t, Wmh_t, out);
}

// round 5
// speedup vs baseline: 2.0753x; 1.0566x over previous
#include <cuda_runtime.h>

#define Tn 128
#define Bn 8
#define En 256
#define Hn 512
#define G4 2048
#define NB2 128
#define NT2 256
#define WSTR 516   // 512 + pad -> 16B-aligned rows
#define NLEAF 8
#define ARRB 8     // release-arrivals per block per barrier
typedef unsigned long long ull;

// ---------------- device scratch ----------------
__device__ float g_xs[Tn * Bn * G4];   // emb@Wih_s + b_s, [(t*8+b)*2048 + col]
__device__ float g_xt[Tn * Bn * G4];   // emb@Wih_t + b_t
__device__ float g_h[2][Bn * Hn];      // double-buffered recurrent state
__device__ unsigned int g_leaf[NLEAF * 64];  // leaf counters, 256B apart

// ---------------- helpers ----------------
__device__ __forceinline__ ull fma2(ull a, ull b, ull c) {
    ull d;
    asm("fma.rn.f32x2 %0, %1, %2, %3;" : "=l"(d) : "l"(a), "l"(b), "l"(c));
    return d;
}
__device__ __forceinline__ float2 up2(ull a) {
    float2 f;
    asm("mov.b64 {%0, %1}, %2;" : "=f"(f.x), "=f"(f.y) : "l"(a));
    return f;
}
__device__ __forceinline__ float sigm(float x) {
    return __frcp_rn(1.f + __expf(-x));
}
__device__ __forceinline__ float tanh_f(float x) {
    return 1.f - 2.f * __frcp_rn(__expf(2.f * x) + 1.f);
}

__device__ __forceinline__ void bar_arrive(int lane) {
    asm volatile("red.release.gpu.global.add.u32 [%0], 1;"
                 :: "l"(&g_leaf[lane * 64]) : "memory");
}
// hot-path poll: NO fence (all cross-block traffic is L2-scope by construction)
__device__ __forceinline__ void bar_poll(unsigned target) {
    unsigned s;
    do {
        s = 0;
#pragma unroll
        for (int i = 0; i < NLEAF; i++) {
            unsigned v;
            asm volatile("ld.relaxed.gpu.global.u32 %0, [%1];"
                         : "=r"(v) : "l"(&g_leaf[i * 64]) : "memory");
            s += v;
        }
    } while (s < target);
}
__device__ __forceinline__ void bar_poll_fence(unsigned target) {
    bar_poll(target);
    asm volatile("fence.acq_rel.gpu;" ::: "memory");
}
__device__ __forceinline__ float4 ld_h4(const float* p) {
    float4 v;
    asm volatile("ld.relaxed.gpu.global.v4.f32 {%0,%1,%2,%3}, [%4];"
                 : "=f"(v.x), "=f"(v.y), "=f"(v.z), "=f"(v.w) : "l"(p) : "memory");
    return v;
}

// ---------------- kernel 1: gathered input GEMM (both matrices via z) ----------------
__global__ void __launch_bounds__(256) input_gemm(const int* __restrict__ tokens,
                                                  const float* __restrict__ etab,
                                                  const float* __restrict__ W0,
                                                  const float* __restrict__ bias0,
                                                  const float* __restrict__ W1,
                                                  const float* __restrict__ bias1) {
    __shared__ float As[16][128];
    __shared__ float Bs[16][128];
    const int which = blockIdx.z;
    const float* W    = which ? W1 : W0;
    const float* bias = which ? bias1 : bias0;
    float* outp = which ? g_xt : g_xs;

    if (blockIdx.x == 0 && blockIdx.y == 0 && blockIdx.z == 0 && threadIdx.x < NLEAF)
        g_leaf[threadIdx.x * 64] = 0u;

    const int m0 = blockIdx.y * 128;
    const int n0 = blockIdx.x * 128;
    const int tid = threadIdx.x;
    const int tr = tid >> 4, tc = tid & 15;

    float acc[8][8];
#pragma unroll
    for (int i = 0; i < 8; i++)
#pragma unroll
        for (int j = 0; j < 8; j++) acc[i][j] = 0.f;

    const int mA0 = tid >> 2;
    const int mA1 = (tid + 256) >> 2;
    const int kq0 = tid & 3;
    const int gm0 = m0 + mA0, gm1 = m0 + mA1;
    const long tok0 = tokens[(gm0 & 7) * Tn + (gm0 >> 3)];
    const long tok1 = tokens[(gm1 & 7) * Tn + (gm1 >> 3)];

    const int kb = tid >> 5;
    const int nq = tid & 31;

    for (int k0 = 0; k0 < En; k0 += 16) {
        float4 a0 = *(const float4*)&etab[tok0 * En + k0 + kq0 * 4];
        float4 a1 = *(const float4*)&etab[tok1 * En + k0 + kq0 * 4];
        As[kq0 * 4 + 0][mA0] = a0.x; As[kq0 * 4 + 1][mA0] = a0.y;
        As[kq0 * 4 + 2][mA0] = a0.z; As[kq0 * 4 + 3][mA0] = a0.w;
        As[kq0 * 4 + 0][mA1] = a1.x; As[kq0 * 4 + 1][mA1] = a1.y;
        As[kq0 * 4 + 2][mA1] = a1.z; As[kq0 * 4 + 3][mA1] = a1.w;

        *(float4*)&Bs[kb][nq * 4]     = *(const float4*)&W[(k0 + kb) * G4 + n0 + nq * 4];
        *(float4*)&Bs[kb + 8][nq * 4] = *(const float4*)&W[(k0 + kb + 8) * G4 + n0 + nq * 4];
        __syncthreads();

#pragma unroll
        for (int k = 0; k < 16; k++) {
            float av[8], bv[8];
            *(float4*)&av[0] = *(const float4*)&As[k][tr * 4];
            *(float4*)&av[4] = *(const float4*)&As[k][64 + tr * 4];
            *(float4*)&bv[0] = *(const float4*)&Bs[k][tc * 4];
            *(float4*)&bv[4] = *(const float4*)&Bs[k][64 + tc * 4];
#pragma unroll
            for (int i = 0; i < 8; i++)
#pragma unroll
                for (int j = 0; j < 8; j++) acc[i][j] += av[i] * bv[j];
        }
        __syncthreads();
    }

#pragma unroll
    for (int i = 0; i < 8; i++) {
        int m = m0 + ((i < 4) ? (tr * 4 + i) : (64 + tr * 4 + i - 4));
#pragma unroll
        for (int jh = 0; jh < 2; jh++) {
            int n = n0 + tc * 4 + jh * 64;
            float4 v;
            v.x = acc[i][jh * 4 + 0] + __ldg(&bias[n + 0]);
            v.y = acc[i][jh * 4 + 1] + __ldg(&bias[n + 1]);
            v.z = acc[i][jh * 4 + 2] + __ldg(&bias[n + 2]);
            v.w = acc[i][jh * 4 + 3] + __ldg(&bias[n + 3]);
            *(float4*)&outp[(long)m * G4 + n] = v;
        }
    }
}

// ---------------- kernel 2: persistent dual-LSTM, 256 threads, weights in regs ----------------
// Block bl owns h-units [bl*4, bl*4+4) => 16 gate cols.
// stage1: (kg = tid>>4 in 0..15, c = tid&15), 32-k slice each, weights in 16 ull regs.
// stage2/activation: tid<128, (c2 = tid>>3, b2 = tid&7).
__global__ void __launch_bounds__(NT2) lstm_kernel(const float* __restrict__ Whh_s,
                                                   const float* __restrict__ Whh_t,
                                                   const float* __restrict__ Wmh_t,
                                                   float* __restrict__ out) {
    extern __shared__ float sm[];
    float* wstage = sm;                  // [16][WSTR] weight staging (transient)
    float* hs     = wstage + 16 * WSTR;  // [8][WSTR]  current h
    float* red    = hs + 8 * WSTR;       // [16][128]  k-group partials
    float* prebuf = red + 16 * 128;      // [128]      pre-activations (c2*8+b2)
    float* cst    = prebuf + 128;        // [32]       c-state
    float* hsnew  = cst + 32;            // [32]       new h staging

    const int tid = threadIdx.x;
    const int bl  = blockIdx.x;
    const int kg  = tid >> 4, c  = tid & 15;   // stage-1 identity
    const int c2  = tid >> 3, b2 = tid & 7;    // stage-2 identity (tid<128)
    const int col2 = (c2 >> 2) * Hn + bl * 4 + (c2 & 3);

    ull wreg[16];

    auto stageW = [&](const float* W) {
        __syncthreads();
        for (int i = tid; i < 16 * Hn; i += NT2) {
            int cc = i & 15, k = i >> 4;
            int cl = (cc >> 2) * Hn + bl * 4 + (cc & 3);
            wstage[cc * WSTR + k] = W[(long)k * G4 + cl];
        }
        __syncthreads();
#pragma unroll
        for (int i = 0; i < 16; i++)
            wreg[i] = *(const ull*)(wstage + c * WSTR + kg * 32 + 2 * i);
    };

    unsigned nbar = 0;
    auto gbar = [&]() {   // cold-path barrier, with acquire fence
        __syncthreads();
        nbar++;
        if (tid < ARRB) bar_arrive(tid);
        if (tid == 0) bar_poll_fence((unsigned)(ARRB * NB2) * nbar);
        __syncthreads();
    };

    auto load_h = [&](int rp) {
#pragma unroll
        for (int i = 0; i < 4; i++) {
            int idx = tid + i * NT2;              // 0..1023
            int bb = idx >> 7, k4 = idx & 127;
            float4 v = ld_h4(&g_h[rp][bb * Hn + k4 * 4]);
            *(float4*)&hs[bb * WSTR + k4 * 4] = v;
        }
    };

    auto stage1 = [&]() {
        float part[8];
#pragma unroll
        for (int b = 0; b < 8; b++) {
            const float* hb = hs + b * WSTR + kg * 32;
            ull a0 = 0ull, a1 = 0ull;
#pragma unroll
            for (int kq = 0; kq < 8; kq++) {
                ulonglong2 hv = *(const ulonglong2*)(hb + kq * 4);
                a0 = fma2(hv.x, wreg[2 * kq], a0);
                a1 = fma2(hv.y, wreg[2 * kq + 1], a1);
            }
            float2 f0 = up2(a0), f1 = up2(a1);
            part[b] = (f0.x + f1.x) + (f0.y + f1.y);
        }
        *(float4*)&red[kg * 128 + c * 8]     = make_float4(part[0], part[1], part[2], part[3]);
        *(float4*)&red[kg * 128 + c * 8 + 4] = make_float4(part[4], part[5], part[6], part[7]);
    };
    auto stage2 = [&](float xv) {   // tid<128 only
        float p = xv;
#pragma unroll
        for (int g = 0; g < 16; g++) p += red[g * 128 + tid];
        return p;
    };

    // xv carried across steps (prefetched during barrier wait)
    float xv = 0.f;

    auto do_step = [&](const float* xbase, const float* xnextbase, float rcv,
                       int t, int rp, int wp, float* outp, bool dobar) {
        load_h(rp);
        __syncthreads();
        stage1();
        __syncthreads();
        if (tid < 128) prebuf[tid] = stage2(xv + rcv);
        __syncthreads();
        nbar++;
        if (tid < 32) {
            int bb = tid >> 2, j = tid & 3;
            float iv = prebuf[(0  + j) * 8 + bb];
            float fv = prebuf[(4  + j) * 8 + bb];
            float gv = prebuf[(8  + j) * 8 + bb];
            float ov = prebuf[(12 + j) * 8 + bb];
            float cn = sigm(fv) * cst[tid] + sigm(iv) * tanh_f(gv);
            float hn = sigm(ov) * tanh_f(cn);
            cst[tid] = cn;
            hsnew[bb * 4 + j] = hn;
            __syncwarp();
            if (tid < 8) {
                float4 v = *(const float4*)&hsnew[tid * 4];
                __stcg((float4*)&g_h[wp][tid * Hn + bl * 4], v);
                if (outp) __stcg((float4*)&outp[(long)(tid * Tn + t) * Hn + bl * 4], v);
                bar_arrive(tid);   // release orders this lane's g_h store
            }
        }
        // prefetch next step's x while waiting (hides DRAM latency)
        if (tid < 128 && xnextbase)
            xv = __ldcg(&xnextbase[(long)(((t + 1) & (Tn - 1)) * Bn + b2) * G4 + col2]);
        if (dobar) {
            if (tid == 0) bar_poll((unsigned)(ARRB * NB2) * nbar);
            __syncthreads();
        }
    };

    // ---- init: weights for shared phase, h=0, c=0 ----
    stageW(Whh_s);
    if (tid < 8)
        __stcg((float4*)&g_h[0][tid * Hn + bl * 4], make_float4(0.f, 0.f, 0.f, 0.f));
    if (tid < 32) cst[tid] = 0.f;
    gbar();

    // ---- shared LSTM (attention is identity: softmax over the broadcast axis
    //      of h_shared sums to 1, so Rt == h_last, constant) ----
    if (tid < 128) xv = __ldcg(&g_xs[(long)(0 * Bn + b2) * G4 + col2]);
    for (int t = 0; t < Tn; t++)
        do_step(g_xs, g_xs, 0.f, t, t & 1, (t & 1) ^ 1, nullptr, true);

    // snapshot h_last (in g_h[0]) into smem
    load_h(0);
    __syncthreads();
    gbar();  // everyone holds h_last -> safe to overwrite g_h[0]

    if (tid < 8)
        __stcg((float4*)&g_h[0][tid * Hn + bl * 4], make_float4(0.f, 0.f, 0.f, 0.f));
    if (tid < 32) cst[tid] = 0.f;

    // rc = h_last @ Wmh_t (constant across task steps)
    stageW(Wmh_t);
    stage1();
    __syncthreads();
    float rcv = (tid < 128) ? stage2(0.f) : 0.f;
    stageW(Whh_t);   // leading syncthreads protects red reads above
    gbar();          // zeros published

    // ---- task LSTM, writing output ----
    if (tid < 128) xv = __ldcg(&g_xt[(long)(0 * Bn + b2) * G4 + col2]);
    for (int t = 0; t < Tn; t++)
        do_step(g_xt, g_xt, rcv, t, t & 1, (t & 1) ^ 1, out, t != Tn - 1);
}

// ---------------- launch ----------------
extern "C" void kernel_launch(void* const* d_in, const int* in_sizes, int n_in,
                              void* d_out, int out_size) {
    const int sh = (n_in == 14) ? 0 : 1;
    const int*   tokens = (const int*)d_in[0];
    const float* etab   = (const float*)d_in[2 - sh];
    const float* Wih_s  = (const float*)d_in[3 - sh];
    const float* Whh_s  = (const float*)d_in[4 - sh];
    const float* b_s    = (const float*)d_in[5 - sh];
    const float* Wih_t  = (const float*)d_in[10 - sh];
    const float* Whh_t  = (const float*)d_in[11 - sh];
    const float* Wmh_t  = (const float*)d_in[12 - sh];
    const float* b_t    = (const float*)d_in[13 - sh];
    float* out = (float*)d_out;

    const int smem2 = (16 * WSTR + 8 * WSTR + 16 * 128 + 128 + 32 + 32) * (int)sizeof(float);
    cudaFuncSetAttribute(lstm_kernel, cudaFuncAttributeMaxDynamicSharedMemorySize, smem2);

    dim3 gg(G4 / 128, (Tn * Bn) / 128, 2);  // (16, 8, 2)
    input_gemm<<<gg, 256>>>(tokens, etab, Wih_s, b_s, Wih_t, b_t);
    lstm_kernel<<<NB2, NT2, smem2>>>(Whh_s, Whh_t, Wmh_t, out);
}

// round 6
// speedup vs baseline: 2.2066x; 1.0632x over previous
#include <cuda_runtime.h>

#define Tn 128
#define Bn 8
#define En 256
#define Hn 512
#define G4 2048
#define NB2 128
#define NT2 256
#define WSTR 516   // 512 + pad -> 16B-aligned rows
typedef unsigned long long ull;

// ---------------- device scratch ----------------
__device__ float g_xs[Tn * Bn * G4];   // emb@Wih_s + b_s, [(t*8+b)*2048 + col]
__device__ float g_xt[Tn * Bn * G4];   // emb@Wih_t + b_t
__device__ float g_h[2][Bn * Hn];      // double-buffered recurrent state
__device__ unsigned int g_cnt;         // single monotonic barrier counter

// ---------------- helpers ----------------
__device__ __forceinline__ ull fma2(ull a, ull b, ull c) {
    ull d;
    asm("fma.rn.f32x2 %0, %1, %2, %3;" : "=l"(d) : "l"(a), "l"(b), "l"(c));
    return d;
}
__device__ __forceinline__ float2 up2(ull a) {
    float2 f;
    asm("mov.b64 {%0, %1}, %2;" : "=f"(f.x), "=f"(f.y) : "l"(a));
    return f;
}
__device__ __forceinline__ float sigm(float x) {
    return __frcp_rn(1.f + __expf(-x));
}
__device__ __forceinline__ float tanh_f(float x) {
    return 1.f - 2.f * __frcp_rn(__expf(2.f * x) + 1.f);
}

__device__ __forceinline__ void bar_arrive() {
    asm volatile("red.release.gpu.global.add.u32 [%0], 1;"
                 :: "l"(&g_cnt) : "memory");
}
__device__ __forceinline__ void bar_poll(unsigned target) {
    unsigned v;
    do {
        asm volatile("ld.relaxed.gpu.global.u32 %0, [%1];"
                     : "=r"(v) : "l"(&g_cnt) : "memory");
    } while (v < target);
}
__device__ __forceinline__ void bar_poll_fence(unsigned target) {
    bar_poll(target);
    asm volatile("fence.acq_rel.gpu;" ::: "memory");
}
__device__ __forceinline__ float4 ld_h4(const float* p) {
    float4 v;
    asm volatile("ld.relaxed.gpu.global.v4.f32 {%0,%1,%2,%3}, [%4];"
                 : "=f"(v.x), "=f"(v.y), "=f"(v.z), "=f"(v.w) : "l"(p) : "memory");
    return v;
}
__device__ __forceinline__ void st_h4(float* p, float4 v) {
    asm volatile("st.relaxed.gpu.global.v4.f32 [%0], {%1,%2,%3,%4};"
                 :: "l"(p), "f"(v.x), "f"(v.y), "f"(v.z), "f"(v.w) : "memory");
}

// ---------------- kernel 1: gathered input GEMM (both matrices via z) ----------------
__global__ void __launch_bounds__(256) input_gemm(const int* __restrict__ tokens,
                                                  const float* __restrict__ etab,
                                                  const float* __restrict__ W0,
                                                  const float* __restrict__ bias0,
                                                  const float* __restrict__ W1,
                                                  const float* __restrict__ bias1) {
    __shared__ float As[16][128];
    __shared__ float Bs[16][128];
    const int which = blockIdx.z;
    const float* W    = which ? W1 : W0;
    const float* bias = which ? bias1 : bias0;
    float* outp = which ? g_xt : g_xs;

    if (blockIdx.x == 0 && blockIdx.y == 0 && blockIdx.z == 0 && threadIdx.x == 0)
        g_cnt = 0u;

    const int m0 = blockIdx.y * 128;
    const int n0 = blockIdx.x * 128;
    const int tid = threadIdx.x;
    const int tr = tid >> 4, tc = tid & 15;

    float acc[8][8];
#pragma unroll
    for (int i = 0; i < 8; i++)
#pragma unroll
        for (int j = 0; j < 8; j++) acc[i][j] = 0.f;

    const int mA0 = tid >> 2;
    const int mA1 = (tid + 256) >> 2;
    const int kq0 = tid & 3;
    const int gm0 = m0 + mA0, gm1 = m0 + mA1;
    const long tok0 = tokens[(gm0 & 7) * Tn + (gm0 >> 3)];
    const long tok1 = tokens[(gm1 & 7) * Tn + (gm1 >> 3)];

    const int kb = tid >> 5;
    const int nq = tid & 31;

    for (int k0 = 0; k0 < En; k0 += 16) {
        float4 a0 = *(const float4*)&etab[tok0 * En + k0 + kq0 * 4];
        float4 a1 = *(const float4*)&etab[tok1 * En + k0 + kq0 * 4];
        As[kq0 * 4 + 0][mA0] = a0.x; As[kq0 * 4 + 1][mA0] = a0.y;
        As[kq0 * 4 + 2][mA0] = a0.z; As[kq0 * 4 + 3][mA0] = a0.w;
        As[kq0 * 4 + 0][mA1] = a1.x; As[kq0 * 4 + 1][mA1] = a1.y;
        As[kq0 * 4 + 2][mA1] = a1.z; As[kq0 * 4 + 3][mA1] = a1.w;

        *(float4*)&Bs[kb][nq * 4]     = *(const float4*)&W[(k0 + kb) * G4 + n0 + nq * 4];
        *(float4*)&Bs[kb + 8][nq * 4] = *(const float4*)&W[(k0 + kb + 8) * G4 + n0 + nq * 4];
        __syncthreads();

#pragma unroll
        for (int k = 0; k < 16; k++) {
            float av[8], bv[8];
            *(float4*)&av[0] = *(const float4*)&As[k][tr * 4];
            *(float4*)&av[4] = *(const float4*)&As[k][64 + tr * 4];
            *(float4*)&bv[0] = *(const float4*)&Bs[k][tc * 4];
            *(float4*)&bv[4] = *(const float4*)&Bs[k][64 + tc * 4];
#pragma unroll
            for (int i = 0; i < 8; i++)
#pragma unroll
                for (int j = 0; j < 8; j++) acc[i][j] += av[i] * bv[j];
        }
        __syncthreads();
    }

#pragma unroll
    for (int i = 0; i < 8; i++) {
        int m = m0 + ((i < 4) ? (tr * 4 + i) : (64 + tr * 4 + i - 4));
#pragma unroll
        for (int jh = 0; jh < 2; jh++) {
            int n = n0 + tc * 4 + jh * 64;
            float4 v;
            v.x = acc[i][jh * 4 + 0] + __ldg(&bias[n + 0]);
            v.y = acc[i][jh * 4 + 1] + __ldg(&bias[n + 1]);
            v.z = acc[i][jh * 4 + 2] + __ldg(&bias[n + 2]);
            v.w = acc[i][jh * 4 + 3] + __ldg(&bias[n + 3]);
            *(float4*)&outp[(long)m * G4 + n] = v;
        }
    }
}

// ---------------- kernel 2: persistent dual-LSTM ----------------
// 128 blocks x 256 threads. Block bl owns h-units [bl*4, bl*4+4) => 16 gate cols.
// stage1: (kg = tid>>4, c = tid&15), 32-k slice, weights in 16 ull regs.
// stage2/activation: tid<128, (c2 = tid>>3, b2 = tid&7).
__global__ void __launch_bounds__(NT2) lstm_kernel(const float* __restrict__ Whh_s,
                                                   const float* __restrict__ Whh_t,
                                                   const float* __restrict__ Wmh_t,
                                                   float* __restrict__ out) {
    extern __shared__ float sm[];
    float* wstage = sm;                  // [16][WSTR] weight staging (transient)
    float* hs     = wstage + 16 * WSTR;  // [8][WSTR]  current h
    float* red    = hs + 8 * WSTR;       // [16][128]  k-group partials
    float* prebuf = red + 16 * 128;      // [128]      pre-activations (c2*8+b2)
    float* cst    = prebuf + 128;        // [32]       c-state
    float* hsnew  = cst + 32;            // [32]       new h staging

    const int tid = threadIdx.x;
    const int bl  = blockIdx.x;
    const int kg  = tid >> 4, c  = tid & 15;   // stage-1 identity
    const int c2  = tid >> 3, b2 = tid & 7;    // stage-2 identity (tid<128)
    const int col2 = (c2 >> 2) * Hn + bl * 4 + (c2 & 3);
    const int krot = (kg & 1) << 2;            // bank-phase rotation per kg-parity

    ull wreg[16];

    auto stageW = [&](const float* W) {
        __syncthreads();
        for (int i = tid; i < 16 * Hn; i += NT2) {
            int cc = i & 15, k = i >> 4;
            int cl = (cc >> 2) * Hn + bl * 4 + (cc & 3);
            wstage[cc * WSTR + k] = W[(long)k * G4 + cl];
        }
        __syncthreads();
#pragma unroll
        for (int i = 0; i < 16; i++)
            wreg[i] = *(const ull*)(wstage + c * WSTR + kg * 32 + 2 * i);
    };

    unsigned nbar = 0;
    auto gbar = [&]() {   // cold-path barrier (acquire fence on exit)
        __syncthreads();
        nbar++;
        if (tid == 0) {
            bar_arrive();
            bar_poll_fence((unsigned)NB2 * nbar);
        }
        __syncthreads();
    };

    auto load_h = [&](int rp) {
#pragma unroll
        for (int i = 0; i < 4; i++) {
            int idx = tid + i * NT2;              // 0..1023
            int bb = idx >> 7, k4 = idx & 127;
            float4 v = ld_h4(&g_h[rp][bb * Hn + k4 * 4]);
            *(float4*)&hs[bb * WSTR + k4 * 4] = v;
        }
    };

    auto stage1 = [&]() {
        float part[8];
#pragma unroll
        for (int b = 0; b < 8; b++) {
            const float* hb = hs + b * WSTR + kg * 32;
            ull a0 = 0ull, a1 = 0ull;
#pragma unroll
            for (int kq = 0; kq < 8; kq++) {
                int kk = (kq + krot) & 7;   // rotate: kg-halves hit disjoint banks
                ulonglong2 hv = *(const ulonglong2*)(hb + kk * 4);
                a0 = fma2(hv.x, wreg[2 * kk], a0);
                a1 = fma2(hv.y, wreg[2 * kk + 1], a1);
            }
            float2 f0 = up2(a0), f1 = up2(a1);
            part[b] = (f0.x + f1.x) + (f0.y + f1.y);
        }
        *(float4*)&red[kg * 128 + c * 8]     = make_float4(part[0], part[1], part[2], part[3]);
        *(float4*)&red[kg * 128 + c * 8 + 4] = make_float4(part[4], part[5], part[6], part[7]);
    };
    auto stage2 = [&](float xv) {   // tid<128 only
        float p = xv;
#pragma unroll
        for (int g = 0; g < 16; g++) p += red[g * 128 + tid];
        return p;
    };

    float xv = 0.f;  // prefetched x(t)

    auto do_step = [&](const float* xnextbase, float rcv,
                       int t, int rp, int wp, float* outp, bool dobar) {
        load_h(rp);
        __syncthreads();
        stage1();
        __syncthreads();
        if (tid < 128) prebuf[tid] = stage2(xv + rcv);
        __syncthreads();
        nbar++;
        if (tid < 32) {
            int bb = tid >> 2, j = tid & 3;
            float iv = prebuf[(0  + j) * 8 + bb];
            float fv = prebuf[(4  + j) * 8 + bb];
            float gv = prebuf[(8  + j) * 8 + bb];
            float ov = prebuf[(12 + j) * 8 + bb];
            float cn = sigm(fv) * cst[tid] + sigm(iv) * tanh_f(gv);
            float hn = sigm(ov) * tanh_f(cn);
            cst[tid] = cn;
            hsnew[bb * 4 + j] = hn;
            __syncwarp();
            if (tid < 8 && outp) {
                float4 v = *(const float4*)&hsnew[tid * 4];
                __stcg((float4*)&outp[(long)(tid * Tn + t) * Hn + bl * 4], v);
            }
            if (tid == 0) {
                // single thread stores all 32 h floats, then ONE release arrival:
                // program order guarantees the release covers these stores.
#pragma unroll
                for (int i = 0; i < 8; i++) {
                    float4 v = *(const float4*)&hsnew[i * 4];
                    st_h4(&g_h[wp][i * Hn + bl * 4], v);
                }
                bar_arrive();
            }
        }
        // prefetch next step's x while waiting (hides latency)
        if (tid < 128 && xnextbase)
            xv = __ldcg(&xnextbase[(long)(((t + 1) & (Tn - 1)) * Bn + b2) * G4 + col2]);
        if (dobar) {
            if (tid == 0) bar_poll((unsigned)NB2 * nbar);
            __syncthreads();
        }
    };

    // ---- init: weights for shared phase, h=0, c=0 ----
    stageW(Whh_s);
    if (tid == 0) {
#pragma unroll
        for (int i = 0; i < 8; i++)
            st_h4(&g_h[0][i * Hn + bl * 4], make_float4(0.f, 0.f, 0.f, 0.f));
    }
    if (tid < 32) cst[tid] = 0.f;
    gbar();

    // ---- shared LSTM (attention is identity: softmax over the broadcast axis
    //      of h_shared sums to 1, so Rt == h_last, constant) ----
    if (tid < 128) xv = __ldcg(&g_xs[(long)(0 * Bn + b2) * G4 + col2]);
    for (int t = 0; t < Tn; t++)
        do_step(g_xs, 0.f, t, t & 1, (t & 1) ^ 1, nullptr, true);

    // snapshot h_last (in g_h[0]) into smem
    load_h(0);
    __syncthreads();
    gbar();  // everyone holds h_last -> safe to overwrite g_h[0]

    if (tid == 0) {
#pragma unroll
        for (int i = 0; i < 8; i++)
            st_h4(&g_h[0][i * Hn + bl * 4], make_float4(0.f, 0.f, 0.f, 0.f));
    }
    if (tid < 32) cst[tid] = 0.f;

    // rc = h_last @ Wmh_t (constant across task steps)
    stageW(Wmh_t);
    stage1();
    __syncthreads();
    float rcv = (tid < 128) ? stage2(0.f) : 0.f;
    stageW(Whh_t);   // leading syncthreads protects red reads above
    gbar();          // zeros published

    // ---- task LSTM, writing output ----
    if (tid < 128) xv = __ldcg(&g_xt[(long)(0 * Bn + b2) * G4 + col2]);
    for (int t = 0; t < Tn; t++)
        do_step(g_xt, rcv, t, t & 1, (t & 1) ^ 1, out, t != Tn - 1);
}

// ---------------- launch ----------------
extern "C" void kernel_launch(void* const* d_in, const int* in_sizes, int n_in,
                              void* d_out, int out_size) {
    const int sh = (n_in == 14) ? 0 : 1;
    const int*   tokens = (const int*)d_in[0];
    const float* etab   = (const float*)d_in[2 - sh];
    const float* Wih_s  = (const float*)d_in[3 - sh];
    const float* Whh_s  = (const float*)d_in[4 - sh];
    const float* b_s    = (const float*)d_in[5 - sh];
    const float* Wih_t  = (const float*)d_in[10 - sh];
    const float* Whh_t  = (const float*)d_in[11 - sh];
    const float* Wmh_t  = (const float*)d_in[12 - sh];
    const float* b_t    = (const float*)d_in[13 - sh];
    float* out = (float*)d_out;

    const int smem2 = (16 * WSTR + 8 * WSTR + 16 * 128 + 128 + 32 + 32) * (int)sizeof(float);
    cudaFuncSetAttribute(lstm_kernel, cudaFuncAttributeMaxDynamicSharedMemorySize, smem2);

    dim3 gg(G4 / 128, (Tn * Bn) / 128, 2);  // (16, 8, 2)
    input_gemm<<<gg, 256>>>(tokens, etab, Wih_s, b_s, Wih_t, b_t);
    lstm_kernel<<<NB2, NT2, smem2>>>(Whh_s, Whh_t, Wmh_t, out);
}